// round 1
// baseline (speedup 1.0000x reference)
#include <cuda_runtime.h>
#include <cuda_fp16.h>

#define SEQ   2048
#define DIN   1024
#define DHID  2048
#define DOUT  512
#define NPROJ 8192   // 4 gates * DHID

// ---- recurrent kernel geometry ----
#define NJ       14            // hidden units per CTA
#define RWARPS   14            // one warp per hidden unit
#define RTHREADS (RWARPS * 32) // 448
#define RGRID    147           // ceil(2048 / 14), <= 148 SMs -> all co-resident
#define SMEM_REC (NJ * 4 * DHID * 2)  // 229376 B of fp16 weights

// ---- device scratch (allocation-free requirement) ----
__device__ float    g_xproj[(size_t)SEQ * NPROJ];        // 64 MB: [t][g*2048+j]
__device__ __half   g_wh[(size_t)4 * DHID * DHID];       // 32 MB: [(g*2048+j)*2048+k]
__device__ float    g_h[2][DHID];                        // double-buffered hidden state
__device__ unsigned g_arrive;                            // monotonic barrier counter

struct Ptrs { const float* W[4]; const float* b[4]; };

// ---------------------------------------------------------------------------
// init: zero h, reset barrier counter (runs every launch -> graph-replay safe)
// ---------------------------------------------------------------------------
__global__ void k_init() {
    int i = blockIdx.x * blockDim.x + threadIdx.x;
    if (i < 2 * DHID) ((float*)g_h)[i] = 0.0f;
    if (i == 0) g_arrive = 0u;
}

// ---------------------------------------------------------------------------
// pack: transpose h-part of each gate weight [3072,2048] -> fp16 [g][j][k]
// 32x32 smem tile keeps both global sides coalesced.
// ---------------------------------------------------------------------------
__global__ void k_pack(Ptrs p) {
    __shared__ float tile[32][33];
    int g  = blockIdx.z;
    int k0 = blockIdx.x * 32;
    int j0 = blockIdx.y * 32;
    // read W[g][(DIN + k0+ty) * DHID + j0+tx]  (coalesced in j)
    tile[threadIdx.y][threadIdx.x] =
        p.W[g][(size_t)(DIN + k0 + threadIdx.y) * DHID + j0 + threadIdx.x];
    __syncthreads();
    // write g_wh[(g, j0+ty, k0+tx)] = W[g][(DIN + k0+tx)][j0+ty]  (coalesced in k)
    g_wh[((size_t)g * DHID + j0 + threadIdx.y) * DHID + k0 + threadIdx.x] =
        __float2half(tile[threadIdx.x][threadIdx.y]);
}

// ---------------------------------------------------------------------------
// xproj GEMM: g_xproj[t][g*2048+j] = b_g[j] + sum_k x[t,k] * W_g[k,j]
// 64x64 tile, BK=16, 256 threads, 4x4 microtile, fp32.
// ---------------------------------------------------------------------------
__global__ __launch_bounds__(256, 2) void k_xproj(const float* __restrict__ x, Ptrs p) {
    __shared__ float As[16][64];   // [k][m]
    __shared__ float Bs[16][68];   // [k][n], pad keeps 16B-aligned rows (68*4=272)
    int n0 = blockIdx.x * 64;
    int m0 = blockIdx.y * 64;
    int g  = blockIdx.x >> 5;          // 64 | 2048 -> gate constant per CTA
    int j0 = n0 & (DHID - 1);
    const float* __restrict__ W = p.W[g];
    int tid = threadIdx.x;
    int tx = tid & 15, ty = tid >> 4;
    float acc[4][4] = {};

    for (int k0 = 0; k0 < DIN; k0 += 16) {
        int lm = tid >> 2, lk = (tid & 3) << 2;
        float4 av = *(const float4*)&x[(size_t)(m0 + lm) * DIN + k0 + lk];
        int bk = tid >> 4, bn = (tid & 15) << 2;
        float4 bv = *(const float4*)&W[(size_t)(k0 + bk) * DHID + j0 + bn];
        As[lk + 0][lm] = av.x;
        As[lk + 1][lm] = av.y;
        As[lk + 2][lm] = av.z;
        As[lk + 3][lm] = av.w;
        *(float4*)&Bs[bk][bn] = bv;
        __syncthreads();
#pragma unroll
        for (int kk = 0; kk < 16; kk++) {
            float4 a = *(const float4*)&As[kk][ty << 2];
            float4 b = *(const float4*)&Bs[kk][tx << 2];
            float am[4] = {a.x, a.y, a.z, a.w};
            float bn2[4] = {b.x, b.y, b.z, b.w};
#pragma unroll
            for (int mm = 0; mm < 4; mm++)
#pragma unroll
                for (int nn = 0; nn < 4; nn++)
                    acc[mm][nn] += am[mm] * bn2[nn];
        }
        __syncthreads();
    }

    const float* bg = p.b[g];
#pragma unroll
    for (int mm = 0; mm < 4; mm++) {
        int m = m0 + (ty << 2) + mm;
#pragma unroll
        for (int nn = 0; nn < 4; nn++) {
            int nl = (tx << 2) + nn;
            g_xproj[(size_t)m * NPROJ + n0 + nl] = acc[mm][nn] + bg[j0 + nl];
        }
    }
}

// ---------------------------------------------------------------------------
// recurrent persistent kernel
// ---------------------------------------------------------------------------
__device__ __forceinline__ float sigm_(float v) { return 1.0f / (1.0f + __expf(-v)); }
__device__ __forceinline__ float tanh_(float v) { return 2.0f / (1.0f + __expf(-2.0f * v)) - 1.0f; }

__global__ void __launch_bounds__(RTHREADS, 1) k_rec() {
    extern __shared__ __half sw[];   // [(jl*4+g)*2048 + k]
    int tid  = threadIdx.x;
    int w    = tid >> 5;
    int lane = tid & 31;
    int j0   = blockIdx.x * NJ;
    int nj   = DHID - j0; if (nj > NJ) nj = NJ;

    // ---- stage this CTA's fp16 weight slice into smem (one time) ----
    {
        int nvec = nj * 4 * (DHID / 8);            // uint4 = 8 halves, 256 per row
        uint4* dst = (uint4*)sw;
        for (int t = tid; t < nvec; t += RTHREADS) {
            int r  = t >> 8;                        // smem row = jl*4+g
            int c  = t & 255;
            int jl = r >> 2, g = r & 3;
            const uint4* src = (const uint4*)(g_wh + ((size_t)g * DHID + j0 + jl) * DHID);
            dst[(r << 8) + c] = src[c];
        }
    }
    __syncthreads();

    bool active = (w < nj);
    int  jg     = j0 + w;
    const __half* wrow = sw + (size_t)(w * 4) * DHID;
    float cst = 0.0f;

#pragma unroll 1
    for (int s = 0; s < SEQ; ++s) {
        const float* hprev = g_h[s & 1];
        float*       hnext = g_h[(s + 1) & 1];

        if (active) {
            const float* xp = g_xproj + (size_t)s * NPROJ + jg;
            float x0 = __ldcg(xp);
            float x1 = __ldcg(xp + DHID);
            float x2 = __ldcg(xp + 2 * DHID);
            float x3 = __ldcg(xp + 3 * DHID);

            float a0 = 0.f, a1 = 0.f, a2 = 0.f, a3 = 0.f;
#pragma unroll
            for (int i = 0; i < 16; i++) {
                int k0 = (i << 7) + (lane << 2);
                float4 hv = __ldcg((const float4*)(hprev + k0));
                {
                    uint2 wv = *(const uint2*)(wrow + k0);
                    float2 f01 = __half22float2(*(const __half2*)&wv.x);
                    float2 f23 = __half22float2(*(const __half2*)&wv.y);
                    a0 += f01.x * hv.x + f01.y * hv.y + f23.x * hv.z + f23.y * hv.w;
                }
                {
                    uint2 wv = *(const uint2*)(wrow + DHID + k0);
                    float2 f01 = __half22float2(*(const __half2*)&wv.x);
                    float2 f23 = __half22float2(*(const __half2*)&wv.y);
                    a1 += f01.x * hv.x + f01.y * hv.y + f23.x * hv.z + f23.y * hv.w;
                }
                {
                    uint2 wv = *(const uint2*)(wrow + 2 * DHID + k0);
                    float2 f01 = __half22float2(*(const __half2*)&wv.x);
                    float2 f23 = __half22float2(*(const __half2*)&wv.y);
                    a2 += f01.x * hv.x + f01.y * hv.y + f23.x * hv.z + f23.y * hv.w;
                }
                {
                    uint2 wv = *(const uint2*)(wrow + 3 * DHID + k0);
                    float2 f01 = __half22float2(*(const __half2*)&wv.x);
                    float2 f23 = __half22float2(*(const __half2*)&wv.y);
                    a3 += f01.x * hv.x + f01.y * hv.y + f23.x * hv.z + f23.y * hv.w;
                }
            }
#pragma unroll
            for (int off = 16; off; off >>= 1) {
                a0 += __shfl_xor_sync(0xffffffffu, a0, off);
                a1 += __shfl_xor_sync(0xffffffffu, a1, off);
                a2 += __shfl_xor_sync(0xffffffffu, a2, off);
                a3 += __shfl_xor_sync(0xffffffffu, a3, off);
            }
            float f  = sigm_(a0 + x0);
            float ig = sigm_(a1 + x1);
            float gg = tanh_(a2 + x2);
            float oo = sigm_(a3 + x3);
            cst = cst * f + ig * gg;
            float hn = tanh_(cst) * oo;
            if (lane == 0) __stcg(hnext + jg, hn);
        }

        if (s < SEQ - 1) {
            __threadfence();          // publish this thread's h stores (L2)
            __syncthreads();          // all warps in CTA done with step s
            if (tid == 0) {
                atomicAdd(&g_arrive, 1u);
                unsigned tgt = (unsigned)(s + 1) * (unsigned)RGRID;
                while (*((volatile unsigned*)&g_arrive) < tgt) { }
            }
            __syncthreads();          // release whole CTA into step s+1
        }
    }
}

// ---------------------------------------------------------------------------
// output: out[o] = b_out[o] + sum_j h_last[j] * W_out[j,o]   (h_last = g_h[0])
// ---------------------------------------------------------------------------
__global__ __launch_bounds__(256) void k_out(const float* __restrict__ Wout,
                                             const float* __restrict__ bout,
                                             float* __restrict__ out) {
    __shared__ float red[4][64];
    int ol  = threadIdx.x & 63;
    int seg = threadIdx.x >> 6;
    int o   = blockIdx.x * 64 + ol;
    const float* h = g_h[0];      // SEQ even -> final h lands in buffer 0
    float acc = 0.0f;
    int kbeg = seg * 512;
#pragma unroll 4
    for (int k = kbeg; k < kbeg + 512; ++k)
        acc += h[k] * Wout[(size_t)k * DOUT + o];
    red[seg][ol] = acc;
    __syncthreads();
    if (seg == 0)
        out[o] = bout[o] + red[0][ol] + red[1][ol] + red[2][ol] + red[3][ol];
}

// ---------------------------------------------------------------------------
extern "C" void kernel_launch(void* const* d_in, const int* in_sizes, int n_in,
                              void* d_out, int out_size) {
    const float* x = (const float*)d_in[0];
    Ptrs p;
    p.W[0] = (const float*)d_in[1]; p.b[0] = (const float*)d_in[2];   // f
    p.W[1] = (const float*)d_in[3]; p.b[1] = (const float*)d_in[4];   // i
    p.W[2] = (const float*)d_in[5]; p.b[2] = (const float*)d_in[6];   // c (g)
    p.W[3] = (const float*)d_in[7]; p.b[3] = (const float*)d_in[8];   // o
    const float* Wout = (const float*)d_in[9];
    const float* bout = (const float*)d_in[10];

    cudaFuncSetAttribute(k_rec, cudaFuncAttributeMaxDynamicSharedMemorySize, SMEM_REC);

    k_init<<<4, 1024>>>();
    k_pack<<<dim3(DHID / 32, DHID / 32, 4), dim3(32, 32)>>>(p);
    k_xproj<<<dim3(NPROJ / 64, SEQ / 64), 256>>>(x, p);
    k_rec<<<RGRID, RTHREADS, SMEM_REC>>>();
    k_out<<<DOUT / 64, 256>>>(Wout, bout, (float*)d_out);
}